// round 5
// baseline (speedup 1.0000x reference)
#include <cuda_runtime.h>
#include <cuda_bf16.h>

// Problem constants
#define BB 8
#define NN 65536
#define PP 12
#define GG 64
#define G3 (GG*GG*GG)               // 262144
#define THREADS 256
#define TOTAL   (BB*PP*NN)          // 6291456
#define NBLOCKS (TOTAL/THREADS)     // 24576
#define BLKS_PER_BATCH (PP*NN/THREADS)   // 3072
#define BLKS_PER_PLANE (NN/THREADS)      // 256

// Scratch (static device arrays — no dynamic allocation anywhere)
__device__ float g_partials[NBLOCKS];
__device__ int   g_counter = 0;     // last-block ticket; self-resets each launch

// ---------------------------------------------------------------------------
// Single fused kernel. Thread f = blockIdx*256+tid maps to the reference's
// flat (b, p*n) order:  b = f/(P*N), plane = (f%(P*N))>>16, j = f&0xFFFF.
// Block-uniform decomposition: each block serves exactly one (b, plane), so
// the plane normal is loaded via broadcast and normalized redundantly per
// thread (rsqrt + Newton, ~1e-7 accurate) — no prep kernel needed.
//
// refl = p - 2*(dot(p,n')+d')*n'
// idx3 = ceil((refl+0.5)*G - 0.5)   (rn adds/muls, no fma fusion)
// idx  = clip(ix*G*G + iy*G + iz, 0, G^3-1)
// term = ||refl - cp[idx]||^2 * (1 - voxel[idx])    (voxel in {0,1})
//
// Unconditional cp gather + multiplicative mask: no divergence, loads issue
// early; L2 has ample headroom (measured 8.8%).
// Ends with deterministic block reduction + last-block fixed-order final sum.
// ---------------------------------------------------------------------------
__global__ __launch_bounds__(THREADS)
void sym_plane_loss_kernel(const float* __restrict__ voxel,
                           const float* __restrict__ points,
                           const float* __restrict__ cp,
                           const float* __restrict__ planes,
                           float* __restrict__ out)
{
    const int blk   = blockIdx.x;
    const int b     = blk / BLKS_PER_BATCH;                 // 0..7
    const int r     = blk - b * BLKS_PER_BATCH;             // 0..3071
    const int plane = r >> 8;                               // 0..11
    const int j     = ((r & 255) << 8) + threadIdx.x;       // 0..65535

    // ---- plane normalization (block-uniform broadcast loads) ----
    const int pbase = (b * PP + plane) * 4;
    const float nx0 = __ldg(planes + pbase + 0);
    const float ny0 = __ldg(planes + pbase + 1);
    const float nz0 = __ldg(planes + pbase + 2);
    const float d0  = __ldg(planes + pbase + 3);
    const float n2  = nx0*nx0 + ny0*ny0 + nz0*nz0;
    float inv = rsqrtf(n2);
    inv = inv * (1.5f - 0.5f * n2 * inv * inv);   // Newton: ~1 ulp
    const float nx = nx0 * inv, ny = ny0 * inv, nz = nz0 * inv, dd = d0 * inv;

    // ---- point load (coalesced: consecutive threads, consecutive j) ----
    const int pidx = (b << 16) + j;
    const float px = __ldg(points + pidx*3 + 0);
    const float py = __ldg(points + pidx*3 + 1);
    const float pz = __ldg(points + pidx*3 + 2);

    // ---- reflection ----
    const float dot = px*nx + py*ny + pz*nz;
    const float s   = 2.0f * (dot + dd);
    const float rx  = px - s * nx;
    const float ry  = py - s * ny;
    const float rz  = pz - s * nz;

    // ---- voxel index (rn ops, no fma fusion; ceil is integral so cast safe) ----
    const int ix = (int)ceilf(__fadd_rn(__fmul_rn(__fadd_rn(rx, 0.5f), (float)GG), -0.5f));
    const int iy = (int)ceilf(__fadd_rn(__fmul_rn(__fadd_rn(ry, 0.5f), (float)GG), -0.5f));
    const int iz = (int)ceilf(__fadd_rn(__fmul_rn(__fadd_rn(rz, 0.5f), (float)GG), -0.5f));
    int idx = ix * (GG*GG) + iy * GG + iz;
    idx = min(max(idx, 0), G3 - 1);

    // ---- gathers (independent, issue together) ----
    const float v  = __ldg(voxel + b * G3 + idx);
    const float* __restrict__ cpp = cp + ((size_t)b * G3 + idx) * 3;
    const float cx = __ldg(cpp + 0);
    const float cy = __ldg(cpp + 1);
    const float cz = __ldg(cpp + 2);

    const float mask = 1.0f - v;        // v in {0,1}; mask^2 == mask
    const float dx = rx - cx, dy = ry - cy, dz = rz - cz;
    const float acc = (dx*dx + dy*dy + dz*dz) * mask;

    // ---- deterministic block reduction ----
    __shared__ float sdata[THREADS];
    __shared__ bool  s_is_last;
    sdata[threadIdx.x] = acc;
    __syncthreads();
    #pragma unroll
    for (int stride = THREADS/2; stride >= 32; stride >>= 1) {
        if (threadIdx.x < stride) sdata[threadIdx.x] += sdata[threadIdx.x + stride];
        __syncthreads();
    }
    if (threadIdx.x < 32) {
        float w = sdata[threadIdx.x];
        #pragma unroll
        for (int off = 16; off > 0; off >>= 1)
            w += __shfl_down_sync(0xFFFFFFFF, w, off);
        if (threadIdx.x == 0) {
            g_partials[blockIdx.x] = w;
            __threadfence();
            const int ticket = atomicAdd(&g_counter, 1);
            s_is_last = (ticket == NBLOCKS - 1);
        }
    }
    __syncthreads();

    // ---- last block: fixed-order final reduction (deterministic) ----
    if (s_is_last) {
        float sacc = 0.0f;
        for (int i = threadIdx.x; i < NBLOCKS; i += THREADS)   // 96 fixed-order adds
            sacc += g_partials[i];
        sdata[threadIdx.x] = sacc;
        __syncthreads();
        #pragma unroll
        for (int stride = THREADS/2; stride >= 32; stride >>= 1) {
            if (threadIdx.x < stride) sdata[threadIdx.x] += sdata[threadIdx.x + stride];
            __syncthreads();
        }
        if (threadIdx.x < 32) {
            float w = sdata[threadIdx.x];
            #pragma unroll
            for (int off = 16; off > 0; off >>= 1)
                w += __shfl_down_sync(0xFFFFFFFF, w, off);
            if (threadIdx.x == 0) {
                out[0] = w / (float)(BB * PP);
                g_counter = 0;   // reset for next graph replay
            }
        }
    }
}

// ---------------------------------------------------------------------------
// Inputs (metadata order = setup_inputs dict order):
//   d_in[0] voxel          (B, G, G, G)   float32
//   d_in[1] points         (B, N, 3)      float32
//   d_in[2] closest_points (B, G^3, 3)    float32
//   d_in[3] planes         (B, P, 4)      float32
// Output: scalar float32
// ---------------------------------------------------------------------------
extern "C" void kernel_launch(void* const* d_in, const int* in_sizes, int n_in,
                              void* d_out, int out_size)
{
    const float* voxel  = (const float*)d_in[0];
    const float* points = (const float*)d_in[1];
    const float* cp     = (const float*)d_in[2];
    const float* planes = (const float*)d_in[3];
    float* out = (float*)d_out;

    sym_plane_loss_kernel<<<NBLOCKS, THREADS>>>(voxel, points, cp, planes, out);
}

// round 7
// speedup vs baseline: 2.4172x; 2.4172x over previous
#include <cuda_runtime.h>
#include <cuda_bf16.h>

// Problem constants
#define BB 8
#define NN 65536
#define PP 12
#define GG 64
#define G3 (GG*GG*GG)               // 262144
#define THREADS 256
#define NBLOCKS ((BB*NN)/THREADS)   // 2048

// Scratch (static device arrays — no dynamic allocation anywhere)
__device__ float g_partials[NBLOCKS];
__device__ int   g_counter = 0;     // last-block ticket; self-resets each launch

// ---------------------------------------------------------------------------
// Single fused kernel. One thread per (b, point); each thread owns the 12
// flat positions f = pt*12+k of the reference's (b, p*n) flattening, so
// plane = f >> 16 (N = 2^16). This reproduces the reference's
// reshape-reinterpretation of the broadcast (b,n,p,3) array into (b,p,n,3).
//
// Planes for this block's batch are normalized once into shared memory with
// EXACT reference arithmetic (sqrtf + division) — R5 proved that approximate
// normalization flips ceil cell boundaries and wrecks accuracy.
//
// refl = p - 2*(dot(p,n)+d)*n
// idx3 = ceil((refl+0.5)*G - 0.5)   (rn adds/muls, no fma fusion)
// idx  = clip(ix*G*G + iy*G + iz, 0, G^3-1)
// term = ||refl - cp[idx]||^2 * (1 - voxel[idx]),  voxel in {0,1}
//
// Phase A: all 12 reflections+indices; then 12 independent voxel gathers
// (MLP=12). Phase B: conditional cp gathers + accumulate. Ends with
// deterministic block reduction + last-block fixed-order final sum.
// ---------------------------------------------------------------------------
__global__ __launch_bounds__(THREADS)
void sym_plane_loss_kernel(const float* __restrict__ voxel,
                           const float* __restrict__ points,
                           const float* __restrict__ cp,
                           const float* __restrict__ planes,
                           float* __restrict__ out)
{
    const int t  = blockIdx.x * THREADS + threadIdx.x;   // 0 .. B*N-1
    const int b  = t >> 16;            // N = 65536; constant within a block
    const int pt = t & 0xFFFF;

    // ---- normalize this batch's 12 planes into shared (exact math) ----
    __shared__ float4 s_planes[PP];
    if (threadIdx.x < PP) {
        const int i = b * PP + threadIdx.x;
        const float nx = planes[i*4+0];
        const float ny = planes[i*4+1];
        const float nz = planes[i*4+2];
        const float d  = planes[i*4+3];
        const float norm = sqrtf(nx*nx + ny*ny + nz*nz);
        s_planes[threadIdx.x] = make_float4(nx/norm, ny/norm, nz/norm, d/norm);
    }
    __syncthreads();

    const float px = __ldg(points + t*3 + 0);
    const float py = __ldg(points + t*3 + 1);
    const float pz = __ldg(points + t*3 + 2);

    const float* __restrict__ vox_b = voxel + b * G3;
    const float* __restrict__ cp_b  = cp    + (size_t)b * G3 * 3;

    const int base_f = pt * PP;

    float rxs[PP], rys[PP], rzs[PP];
    int   idxs[PP];
    float vs[PP];

    // ---- Phase A: reflections + indices ----
    #pragma unroll
    for (int k = 0; k < PP; k++) {
        const int f     = base_f + k;
        const int plane = f >> 16;          // f / N, 0..11 within batch
        const float4 n4 = s_planes[plane];

        const float dot = px*n4.x + py*n4.y + pz*n4.z;
        const float s   = 2.0f * (dot + n4.w);
        const float rx  = px - s * n4.x;
        const float ry  = py - s * n4.y;
        const float rz  = pz - s * n4.z;

        const int ix = (int)ceilf(__fadd_rn(__fmul_rn(__fadd_rn(rx, 0.5f), (float)GG), -0.5f));
        const int iy = (int)ceilf(__fadd_rn(__fmul_rn(__fadd_rn(ry, 0.5f), (float)GG), -0.5f));
        const int iz = (int)ceilf(__fadd_rn(__fmul_rn(__fadd_rn(rz, 0.5f), (float)GG), -0.5f));

        int idx = ix * (GG*GG) + iy * GG + iz;
        idx = min(max(idx, 0), G3 - 1);

        rxs[k] = rx; rys[k] = ry; rzs[k] = rz;
        idxs[k] = idx;
    }

    // ---- batched voxel gathers: 12 independent LDGs, MLP=12 ----
    #pragma unroll
    for (int k = 0; k < PP; k++) {
        vs[k] = __ldg(vox_b + idxs[k]);
    }

    // ---- Phase B: masked cp gathers + accumulate ----
    float acc = 0.0f;
    #pragma unroll
    for (int k = 0; k < PP; k++) {
        if (vs[k] == 0.0f) {
            const int idx = idxs[k];
            const float cx = __ldg(cp_b + idx*3 + 0);
            const float cy = __ldg(cp_b + idx*3 + 1);
            const float cz = __ldg(cp_b + idx*3 + 2);
            const float dx = rxs[k] - cx;
            const float dy = rys[k] - cy;
            const float dz = rzs[k] - cz;
            acc += dx*dx + dy*dy + dz*dz;
        }
    }

    // ---- deterministic block reduction ----
    __shared__ float sdata[THREADS];
    __shared__ bool  s_is_last;
    sdata[threadIdx.x] = acc;
    __syncthreads();
    #pragma unroll
    for (int stride = THREADS/2; stride >= 32; stride >>= 1) {
        if (threadIdx.x < stride) sdata[threadIdx.x] += sdata[threadIdx.x + stride];
        __syncthreads();
    }
    if (threadIdx.x < 32) {
        float w = sdata[threadIdx.x];
        #pragma unroll
        for (int off = 16; off > 0; off >>= 1)
            w += __shfl_down_sync(0xFFFFFFFF, w, off);
        if (threadIdx.x == 0) {
            g_partials[blockIdx.x] = w;
            __threadfence();
            const int ticket = atomicAdd(&g_counter, 1);
            s_is_last = (ticket == NBLOCKS - 1);
        }
    }
    __syncthreads();

    // ---- last block: fixed-order final reduction (deterministic) ----
    if (s_is_last) {
        float sacc = 0.0f;
        #pragma unroll
        for (int i = threadIdx.x; i < NBLOCKS; i += THREADS)   // 8 fixed-order adds
            sacc += g_partials[i];
        sdata[threadIdx.x] = sacc;
        __syncthreads();
        #pragma unroll
        for (int stride = THREADS/2; stride >= 32; stride >>= 1) {
            if (threadIdx.x < stride) sdata[threadIdx.x] += sdata[threadIdx.x + stride];
            __syncthreads();
        }
        if (threadIdx.x < 32) {
            float w = sdata[threadIdx.x];
            #pragma unroll
            for (int off = 16; off > 0; off >>= 1)
                w += __shfl_down_sync(0xFFFFFFFF, w, off);
            if (threadIdx.x == 0) {
                out[0] = w / (float)(BB * PP);
                g_counter = 0;   // reset for next graph replay
            }
        }
    }
}

// ---------------------------------------------------------------------------
// Inputs (metadata order = setup_inputs dict order):
//   d_in[0] voxel          (B, G, G, G)   float32
//   d_in[1] points         (B, N, 3)      float32
//   d_in[2] closest_points (B, G^3, 3)    float32
//   d_in[3] planes         (B, P, 4)      float32
// Output: scalar float32
// ---------------------------------------------------------------------------
extern "C" void kernel_launch(void* const* d_in, const int* in_sizes, int n_in,
                              void* d_out, int out_size)
{
    const float* voxel  = (const float*)d_in[0];
    const float* points = (const float*)d_in[1];
    const float* cp     = (const float*)d_in[2];
    const float* planes = (const float*)d_in[3];
    float* out = (float*)d_out;

    sym_plane_loss_kernel<<<NBLOCKS, THREADS>>>(voxel, points, cp, planes, out);
}

// round 8
// speedup vs baseline: 2.5369x; 1.0495x over previous
#include <cuda_runtime.h>
#include <cuda_bf16.h>

// Problem constants
#define BB 8
#define NN 65536
#define PP 12
#define GG 64
#define G3 (GG*GG*GG)               // 262144
#define THREADS 256
#define NBLOCKS ((BB*NN)/THREADS)   // 2048

// Scratch (static device arrays — no dynamic allocation anywhere)
__device__ float g_partials[NBLOCKS];
__device__ int   g_counter = 0;     // last-block ticket; self-resets each launch

// ---------------------------------------------------------------------------
// Single fused kernel. One thread per (b, point); each thread owns the 12
// flat positions f = pt*12+k of the reference's (b, p*n) flattening, so
// plane = f >> 16 (N = 2^16). This reproduces the reference's
// reshape-reinterpretation of the broadcast (b,n,p,3) array into (b,p,n,3).
//
// Register diet (R7 lesson: occ was reg-limited to 4 blocks/SM at 59 regs):
// Phase A stores only the reflection scalar s[k] (r = p - s*n is recomputed
// in Phase B from shared-memory normals with the SAME fmul/fsub sequence on
// the SAME values -> bit-identical). __launch_bounds__(256,5) caps at 48
// regs -> 5 blocks/SM, occ ~62%.
//
// Planes normalized once per block in shared with EXACT reference arithmetic
// (sqrtf + division) — R5 proved approximate normalization flips ceil cell
// boundaries and wrecks accuracy.
//
// refl = p - 2*(dot(p,n)+d)*n
// idx3 = ceil((refl+0.5)*G - 0.5)   (rn adds/muls, no fma fusion)
// idx  = clip(ix*G*G + iy*G + iz, 0, G^3-1)
// term = ||refl - cp[idx]||^2 * (1 - voxel[idx]),  voxel in {0,1}
// ---------------------------------------------------------------------------
__global__ __launch_bounds__(THREADS, 5)
void sym_plane_loss_kernel(const float* __restrict__ voxel,
                           const float* __restrict__ points,
                           const float* __restrict__ cp,
                           const float* __restrict__ planes,
                           float* __restrict__ out)
{
    const int t  = blockIdx.x * THREADS + threadIdx.x;   // 0 .. B*N-1
    const int b  = t >> 16;            // N = 65536; constant within a block
    const int pt = t & 0xFFFF;

    // ---- normalize this batch's 12 planes into shared (exact math) ----
    __shared__ float4 s_planes[PP];
    if (threadIdx.x < PP) {
        const int i = b * PP + threadIdx.x;
        const float nx = planes[i*4+0];
        const float ny = planes[i*4+1];
        const float nz = planes[i*4+2];
        const float d  = planes[i*4+3];
        const float norm = sqrtf(nx*nx + ny*ny + nz*nz);
        s_planes[threadIdx.x] = make_float4(nx/norm, ny/norm, nz/norm, d/norm);
    }
    __syncthreads();

    const float px = __ldg(points + t*3 + 0);
    const float py = __ldg(points + t*3 + 1);
    const float pz = __ldg(points + t*3 + 2);

    const float* __restrict__ vox_b = voxel + b * G3;
    const float* __restrict__ cp_b  = cp    + (size_t)b * G3 * 3;

    const int base_f = pt * PP;

    float ss[PP];        // reflection scalar s = 2*(dot+d) per plane
    int   idxs[PP];
    float vs[PP];

    // ---- Phase A: reflections + indices (store only s + idx) ----
    #pragma unroll
    for (int k = 0; k < PP; k++) {
        const int f     = base_f + k;
        const int plane = f >> 16;          // f / N, 0..11 within batch
        const float4 n4 = s_planes[plane];

        const float dot = px*n4.x + py*n4.y + pz*n4.z;
        const float s   = 2.0f * (dot + n4.w);
        const float rx  = px - s * n4.x;
        const float ry  = py - s * n4.y;
        const float rz  = pz - s * n4.z;

        const int ix = (int)ceilf(__fadd_rn(__fmul_rn(__fadd_rn(rx, 0.5f), (float)GG), -0.5f));
        const int iy = (int)ceilf(__fadd_rn(__fmul_rn(__fadd_rn(ry, 0.5f), (float)GG), -0.5f));
        const int iz = (int)ceilf(__fadd_rn(__fmul_rn(__fadd_rn(rz, 0.5f), (float)GG), -0.5f));

        int idx = ix * (GG*GG) + iy * GG + iz;
        idx = min(max(idx, 0), G3 - 1);

        ss[k]   = s;
        idxs[k] = idx;
    }

    // ---- batched voxel gathers: 12 independent LDGs, MLP=12 ----
    #pragma unroll
    for (int k = 0; k < PP; k++) {
        vs[k] = __ldg(vox_b + idxs[k]);
    }

    // ---- Phase B: masked cp gathers + accumulate (refl recomputed exactly) ----
    float acc = 0.0f;
    #pragma unroll
    for (int k = 0; k < PP; k++) {
        if (vs[k] == 0.0f) {
            const int f     = base_f + k;
            const float4 n4 = s_planes[f >> 16];
            const float s   = ss[k];
            const float rx  = px - s * n4.x;   // identical ops/values as Phase A
            const float ry  = py - s * n4.y;
            const float rz  = pz - s * n4.z;

            const int idx = idxs[k];
            const float cx = __ldg(cp_b + idx*3 + 0);
            const float cy = __ldg(cp_b + idx*3 + 1);
            const float cz = __ldg(cp_b + idx*3 + 2);
            const float dx = rx - cx;
            const float dy = ry - cy;
            const float dz = rz - cz;
            acc += dx*dx + dy*dy + dz*dz;
        }
    }

    // ---- deterministic block reduction ----
    __shared__ float sdata[THREADS];
    __shared__ bool  s_is_last;
    sdata[threadIdx.x] = acc;
    __syncthreads();
    #pragma unroll
    for (int stride = THREADS/2; stride >= 32; stride >>= 1) {
        if (threadIdx.x < stride) sdata[threadIdx.x] += sdata[threadIdx.x + stride];
        __syncthreads();
    }
    if (threadIdx.x < 32) {
        float w = sdata[threadIdx.x];
        #pragma unroll
        for (int off = 16; off > 0; off >>= 1)
            w += __shfl_down_sync(0xFFFFFFFF, w, off);
        if (threadIdx.x == 0) {
            g_partials[blockIdx.x] = w;
            __threadfence();
            const int ticket = atomicAdd(&g_counter, 1);
            s_is_last = (ticket == NBLOCKS - 1);
        }
    }
    __syncthreads();

    // ---- last block: fixed-order final reduction (deterministic) ----
    if (s_is_last) {
        float sacc = 0.0f;
        #pragma unroll
        for (int i = threadIdx.x; i < NBLOCKS; i += THREADS)   // 8 fixed-order adds
            sacc += g_partials[i];
        sdata[threadIdx.x] = sacc;
        __syncthreads();
        #pragma unroll
        for (int stride = THREADS/2; stride >= 32; stride >>= 1) {
            if (threadIdx.x < stride) sdata[threadIdx.x] += sdata[threadIdx.x + stride];
            __syncthreads();
        }
        if (threadIdx.x < 32) {
            float w = sdata[threadIdx.x];
            #pragma unroll
            for (int off = 16; off > 0; off >>= 1)
                w += __shfl_down_sync(0xFFFFFFFF, w, off);
            if (threadIdx.x == 0) {
                out[0] = w / (float)(BB * PP);
                g_counter = 0;   // reset for next graph replay
            }
        }
    }
}

// ---------------------------------------------------------------------------
// Inputs (metadata order = setup_inputs dict order):
//   d_in[0] voxel          (B, G, G, G)   float32
//   d_in[1] points         (B, N, 3)      float32
//   d_in[2] closest_points (B, G^3, 3)    float32
//   d_in[3] planes         (B, P, 4)      float32
// Output: scalar float32
// ---------------------------------------------------------------------------
extern "C" void kernel_launch(void* const* d_in, const int* in_sizes, int n_in,
                              void* d_out, int out_size)
{
    const float* voxel  = (const float*)d_in[0];
    const float* points = (const float*)d_in[1];
    const float* cp     = (const float*)d_in[2];
    const float* planes = (const float*)d_in[3];
    float* out = (float*)d_out;

    sym_plane_loss_kernel<<<NBLOCKS, THREADS>>>(voxel, points, cp, planes, out);
}